// round 2
// baseline (speedup 1.0000x reference)
#include <cuda_runtime.h>

#define NN      50000      // nodes
#define NIN     128        // node in-dim
#define NOUT    64         // node out-dim
#define EIN     32         // edge feat dim
#define NE      400000     // undirected edges
#define ND      (2*NE)     // directed edges
#define ALPHA_L 0.2f
#define EPSV    1e-12f
#define NPART   256
#define FULLM   0xffffffffu

// ---------------- scratch (device globals; no allocation allowed) -------------
__device__ float  g_hv[NN * NOUT];     // h_v
__device__ float  g_s1[NN];            // h_v . a[0:64]
__device__ float  g_s2[NN];            // h_v . a[64:128]
__device__ float  g_hn[NN];            // ||h_v||
__device__ float  g_t[NE];             // edge_fts . a[128:160]
__device__ int    g_cnt[NN];           // degree histogram
__device__ int    g_off[NN + 1];       // CSR offsets
__device__ int    g_cur[NN];           // scatter cursors
__device__ int    g_dst[ND];           // CSR: dst per directed edge
__device__ float  g_r[ND];             // CSR: s2[dst] + t[u]
__device__ double g_psum[NPART];       // variance partials
__device__ double g_psq[NPART];

// ---------------- k0: zero counters + partials ---------------------------------
__global__ void k0_zero() {
    int stride = gridDim.x * blockDim.x;
    int tid = blockIdx.x * blockDim.x + threadIdx.x;
    for (int i = tid; i < NN; i += stride) g_cnt[i] = 0;
    if (tid < NPART) { g_psum[tid] = 0.0; g_psq[tid] = 0.0; }
}

// ---------------- k1: h_v = node_fts @ W + b, fused s1/s2/||h_v|| ---------------
// 256 threads, 16 nodes/block. Thread = (ng in 0..3, col c in 0..63); each thread
// computes 4 nodes' column c. Then warp-per-2-nodes reduces scalars from smem tile.
__global__ void k1_gemm(const float* __restrict__ nf,
                        const float* __restrict__ W,
                        const float* __restrict__ b,
                        const float* __restrict__ an) {
    __shared__ float Ws[NIN * NOUT];     // 32 KB
    __shared__ float nfs[16 * NIN];      // 8 KB
    __shared__ float hvt[16 * NOUT];     // 4 KB
    int tid = threadIdx.x;
    int base = blockIdx.x * 16;

    for (int i = tid; i < (NIN * NOUT) / 4; i += 256)
        ((float4*)Ws)[i] = ((const float4*)W)[i];
    for (int i = tid; i < (16 * NIN) / 4; i += 256)
        ((float4*)nfs)[i] = ((const float4*)(nf + (long)base * NIN))[i];
    __syncthreads();

    int c = tid & 63;
    int ng = tid >> 6;
    const float* nb = &nfs[ng * 4 * NIN];

    float a0 = 0.f, a1 = 0.f, a2 = 0.f, a3 = 0.f;
#pragma unroll 8
    for (int k = 0; k < NIN; k++) {
        float w = Ws[k * NOUT + c];
        a0 += nb[k]         * w;
        a1 += nb[NIN + k]   * w;
        a2 += nb[2*NIN + k] * w;
        a3 += nb[3*NIN + k] * w;
    }
    float bc = b[c];
    a0 += bc; a1 += bc; a2 += bc; a3 += bc;
    int v = base + ng * 4;
    g_hv[(long)v * NOUT + c]       = a0;  hvt[(ng*4+0) * NOUT + c] = a0;
    g_hv[(long)(v+1) * NOUT + c]   = a1;  hvt[(ng*4+1) * NOUT + c] = a1;
    g_hv[(long)(v+2) * NOUT + c]   = a2;  hvt[(ng*4+2) * NOUT + c] = a2;
    g_hv[(long)(v+3) * NOUT + c]   = a3;  hvt[(ng*4+3) * NOUT + c] = a3;
    __syncthreads();

    // 8 warps x 2 nodes each: per-node scalars from smem tile
    int wp = tid >> 5, l = tid & 31;
    float a1x = __ldg(&an[2*l]),      a1y = __ldg(&an[2*l+1]);
    float a2x = __ldg(&an[64 + 2*l]), a2y = __ldg(&an[64 + 2*l+1]);
#pragma unroll
    for (int i = 0; i < 2; i++) {
        int n = wp * 2 + i;
        float2 h = ((const float2*)hvt)[n * 32 + l];
        float s1 = h.x * a1x + h.y * a1y;
        float s2 = h.x * a2x + h.y * a2y;
        float sq = h.x * h.x + h.y * h.y;
#pragma unroll
        for (int o = 16; o; o >>= 1) {
            s1 += __shfl_down_sync(FULLM, s1, o);
            s2 += __shfl_down_sync(FULLM, s2, o);
            sq += __shfl_down_sync(FULLM, sq, o);
        }
        if (l == 0) {
            int node = base + n;
            g_s1[node] = s1; g_s2[node] = s2; g_hn[node] = sqrtf(sq);
        }
    }
}

// ---------------- k2: t[u] = edge_fts[u] . a[128:160], coalesced ----------------
// Warp handles 4 rows: lane l loads float4 (flat idx row0*8+l), owns row row0+l/8,
// quarter l%8; xor-shuffle reduce over the 8 lanes of each row.
__global__ void k2_edgedot(const float* __restrict__ ef,
                           const float* __restrict__ an) {
    int w = (blockIdx.x * blockDim.x + threadIdx.x) >> 5;
    int l = threadIdx.x & 31;
    int row0 = w * 4;
    if (row0 >= NE) return;
    float4 v = ((const float4*)ef)[(long)row0 * 8 + l];
    const float* a3 = an + 2 * NOUT;
    int q = l & 7;
    float s = v.x * __ldg(&a3[4*q])   + v.y * __ldg(&a3[4*q+1])
            + v.z * __ldg(&a3[4*q+2]) + v.w * __ldg(&a3[4*q+3]);
    s += __shfl_xor_sync(FULLM, s, 4);
    s += __shfl_xor_sync(FULLM, s, 2);
    s += __shfl_xor_sync(FULLM, s, 1);
    if (q == 0) g_t[row0 + (l >> 3)] = s;
}

// ---------------- kA: degree histogram ------------------------------------------
// Directed edges: each undirected edge (x,y) contributes src=x and src=y.
__global__ void kA_hist(const int* __restrict__ p) {
    int u = blockIdx.x * blockDim.x + threadIdx.x;
    if (u >= NE) return;
    int2 xy = ((const int2*)p)[u];
    atomicAdd(&g_cnt[xy.x], 1);
    atomicAdd(&g_cnt[xy.y], 1);
}

// ---------------- kB: exclusive scan -> offsets + cursors -----------------------
__global__ void kB_scan() {
    __shared__ int sums[1024];
    const int CH = (NN + 1023) / 1024;   // 49
    int t = threadIdx.x;
    int s = 0;
    for (int k = 0; k < CH; k++) {
        int idx = t * CH + k;
        if (idx < NN) s += g_cnt[idx];
    }
    sums[t] = s;
    __syncthreads();
    for (int o = 1; o < 1024; o <<= 1) {
        int v = (t >= o) ? sums[t - o] : 0;
        __syncthreads();
        sums[t] += v;
        __syncthreads();
    }
    int pre = (t > 0) ? sums[t - 1] : 0;
    for (int k = 0; k < CH; k++) {
        int idx = t * CH + k;
        if (idx < NN) {
            int c = g_cnt[idx];
            g_off[idx] = pre;
            g_cur[idx] = pre;
            pre += c;
        }
    }
    if (t == 1023) g_off[NN] = pre;
}

// ---------------- kC: scatter CSR entries (dst, r = s2[dst]+t[u]) ---------------
__global__ void kC_scatter(const int* __restrict__ p) {
    int u = blockIdx.x * blockDim.x + threadIdx.x;
    if (u >= NE) return;
    int2 xy = ((const int2*)p)[u];
    float tu = g_t[u];
    float ry = g_s2[xy.y] + tu;   // direction src=x, dst=y
    float rx = g_s2[xy.x] + tu;   // direction src=y, dst=x
    int pos1 = atomicAdd(&g_cur[xy.x], 1);
    g_dst[pos1] = xy.y;  g_r[pos1] = ry;
    int pos2 = atomicAdd(&g_cur[xy.y], 1);
    g_dst[pos2] = xy.x;  g_r[pos2] = rx;
}

// ---------------- kD: fused per-node attention + msg gather + output ------------
// Warp per node. Pass 1: sum exp(leaky(s1[v]+r)). Pass 2: recompute an, gather
// h[dst], accumulate msg in registers, variance partials. Then normalize + write.
__global__ void kD_node(float* __restrict__ out, const float* __restrict__ scale) {
    __shared__ float ssum[8], ssq[8];
    int wp = threadIdx.x >> 5, l = threadIdx.x & 31;
    int v = blockIdx.x * 8 + wp;
    float wsum = 0.f, wsq = 0.f;
    if (v < NN) {
        int start = g_off[v];
        int deg   = g_off[v + 1] - start;
        float s1v = g_s1[v];

        // pass 1: attsum
        float esum = 0.f;
        for (int i = l; i < deg; i += 32) {
            float lg = s1v + __ldg(&g_r[start + i]);
            float lr = (lg > 0.f) ? lg : ALPHA_L * lg;
            esum += __expf(lr);
        }
#pragma unroll
        for (int o = 16; o; o >>= 1) esum += __shfl_xor_sync(FULLM, esum, o);
        float attlog = __logf(esum);

        // pass 2: msg accumulate
        float2 m = make_float2(0.f, 0.f);
        for (int bse = 0; bse < deg; bse += 32) {
            int i = bse + l;
            float an_l = 0.f; int dst_l = 0;
            if (i < deg) {
                float lg = s1v + __ldg(&g_r[start + i]);
                float lr = (lg > 0.f) ? lg : ALPHA_L * lg;
                an_l = lr - attlog;
                dst_l = __ldg(&g_dst[start + i]);
                wsum += an_l; wsq += an_l * an_l;
            }
            int cnt = min(32, deg - bse);
            for (int e = 0; e < cnt; e++) {
                float an = __shfl_sync(FULLM, an_l, e);
                int  dst = __shfl_sync(FULLM, dst_l, e);
                float2 h = ((const float2*)g_hv)[(long)dst * 32 + l];
                m.x += h.x * an;
                m.y += h.y * an;
            }
        }

        // normalize + output
        float sq = m.x * m.x + m.y * m.y;
#pragma unroll
        for (int o = 16; o; o >>= 1) sq += __shfl_xor_sync(FULLM, sq, o);
        float rn = g_hn[v] * __ldg(scale) / fmaxf(sqrtf(sq), EPSV);
        float2 h = ((const float2*)g_hv)[(long)v * 32 + l];
        float2* orow = (float2*)(out + (long)v * 128);
        orow[l]      = h;
        orow[32 + l] = make_float2(m.x * rn, m.y * rn);
    }
    // variance partials: warp reduce (each an counted once by its owner lane)
#pragma unroll
    for (int o = 16; o; o >>= 1) {
        wsum += __shfl_xor_sync(FULLM, wsum, o);
        wsq  += __shfl_xor_sync(FULLM, wsq,  o);
    }
    if (l == 0) { ssum[wp] = wsum; ssq[wp] = wsq; }
    __syncthreads();
    if (threadIdx.x == 0) {
        float bs = 0.f, bq = 0.f;
#pragma unroll
        for (int i = 0; i < 8; i++) { bs += ssum[i]; bq += ssq[i]; }
        atomicAdd(&g_psum[blockIdx.x & (NPART - 1)], (double)bs);
        atomicAdd(&g_psq [blockIdx.x & (NPART - 1)], (double)bq);
    }
}

// ---------------- k5: variance -> out[NN*128] ------------------------------------
__global__ void k5_var(float* __restrict__ out) {
    __shared__ double s[NPART], q[NPART];
    int t = threadIdx.x;
    s[t] = g_psum[t]; q[t] = g_psq[t];
    __syncthreads();
    for (int o = NPART / 2; o; o >>= 1) {
        if (t < o) { s[t] += s[t + o]; q[t] += q[t + o]; }
        __syncthreads();
    }
    if (t == 0) {
        double E = (double)ND;
        double var = (q[0] - s[0] * s[0] / E) / (E - 1.0);
        out[(long)NN * 128] = (float)var;
    }
}

// ---------------- launch -----------------------------------------------------------
extern "C" void kernel_launch(void* const* d_in, const int* in_sizes, int n_in,
                              void* d_out, int out_size) {
    const float* nf    = (const float*)d_in[0];  // node_fts [50000,128]
    const float* ef    = (const float*)d_in[1];  // edge_fts [400000,32]
    const int*   edges = (const int*)  d_in[2];  // edges [2,400000] (flat)
    const float* W     = (const float*)d_in[3];  // [128,64]
    const float* b     = (const float*)d_in[4];  // [64]
    const float* an    = (const float*)d_in[5];  // a_node [160]
    const float* scale = (const float*)d_in[6];  // scalar
    float* out = (float*)d_out;

    k0_zero   <<<256, 256>>>();
    k1_gemm   <<<NN/16, 256>>>(nf, W, b, an);
    k2_edgedot<<<(NE/4 + 7)/8, 256>>>(ef, an);          // 8 warps/block, 4 rows/warp
    kA_hist   <<<(NE + 255)/256, 256>>>(edges);
    kB_scan   <<<1, 1024>>>();
    kC_scatter<<<(NE + 255)/256, 256>>>(edges);
    kD_node   <<<(NN + 7)/8, 256>>>(out, scale);
    k5_var    <<<1, NPART>>>(out);
}

// round 3
// speedup vs baseline: 1.6276x; 1.6276x over previous
#include <cuda_runtime.h>

#define NN      50000      // nodes
#define NIN     128        // node in-dim
#define NOUT    64         // node out-dim
#define EIN     32         // edge feat dim
#define NE      400000     // undirected edges
#define ND      (2*NE)     // directed edges
#define ALPHA_L 0.2f
#define EPSV    1e-12f
#define NPART   256
#define FULLM   0xffffffffu

// ---------------- scratch (device globals) -------------------------------------
__device__ __align__(16) float g_hv[NN * NOUT];   // h_v
__device__ __align__(16) float g_msg[NN * NOUT];  // segment sum by src
__device__ float  g_s1[NN];
__device__ float  g_s2[NN];
__device__ float  g_hn[NN];
__device__ float  g_attsum[NN];
__device__ float  g_t[NE];
__device__ float  g_lr[ND];
__device__ double g_psum[NPART];
__device__ double g_psq[NPART];

// vector RED: 4 floats in one L2 atomic op (sm_90+)
__device__ __forceinline__ void red_v4(float* addr, float4 v) {
    asm volatile("red.global.add.v4.f32 [%0], {%1,%2,%3,%4};"
                 :: "l"(addr), "f"(v.x), "f"(v.y), "f"(v.z), "f"(v.w) : "memory");
}

// ---------------- k0: zero accumulators ----------------------------------------
__global__ void k0_zero() {
    int stride = gridDim.x * blockDim.x;
    int tid = blockIdx.x * blockDim.x + threadIdx.x;
    float4 z = make_float4(0.f, 0.f, 0.f, 0.f);
    for (int i = tid; i < (NN * NOUT) / 4; i += stride) ((float4*)g_msg)[i] = z;
    for (int i = tid; i < NN; i += stride) g_attsum[i] = 0.f;
    if (tid < NPART) { g_psum[tid] = 0.0; g_psq[tid] = 0.0; }
}

// ---------------- k1: h_v = nf @ W + b, fused s1/s2/||h_v|| ----------------------
// 256 threads, 128 nodes/block. Thread tile: 8 nodes x 4 cols.
// cg = tid&15 (col group), ng = tid>>4 (node group). A reads broadcast within
// half-warp; B read is one LDS.128. FMA-bound (~32 FFMA per 3 LDS).
__global__ void k1_gemm(const float* __restrict__ nf,
                        const float* __restrict__ W,
                        const float* __restrict__ b,
                        const float* __restrict__ an) {
    extern __shared__ float sm[];
    float* Ws = sm;            // 128*64   = 8192 floats (32 KB)
    float* Ns = sm + 8192;     // 128*128  = 16384 floats (64 KB)
    int tid = threadIdx.x;
    int base = blockIdx.x * 128;

    for (int i = tid; i < (NIN * NOUT) / 4; i += 256)
        ((float4*)Ws)[i] = ((const float4*)W)[i];
    // node tile (zero-pad past NN)
    for (int i = tid; i < (128 * NIN) / 4; i += 256) {
        int node = base + (i >> 5);                 // 32 float4 per row
        float4 v = make_float4(0.f, 0.f, 0.f, 0.f);
        if (node < NN) v = ((const float4*)nf)[(long)node * 32 + (i & 31)];
        ((float4*)Ns)[i] = v;
    }
    __syncthreads();

    int cg = tid & 15;         // 4 cols each
    int ng = tid >> 4;         // 8 nodes each
    const float* nb = &Ns[ng * 8 * NIN];

    float4 acc[8];
#pragma unroll
    for (int n = 0; n < 8; n++) acc[n] = make_float4(0.f, 0.f, 0.f, 0.f);

#pragma unroll 4
    for (int k = 0; k < NIN; k++) {
        float4 wv = *(const float4*)&Ws[k * NOUT + cg * 4];
#pragma unroll
        for (int n = 0; n < 8; n++) {
            float av = nb[n * NIN + k];
            acc[n].x += av * wv.x;
            acc[n].y += av * wv.y;
            acc[n].z += av * wv.z;
            acc[n].w += av * wv.w;
        }
    }

    float4 bv = *(const float4*)&b[cg * 4];
    __syncthreads();                         // done reading Ns; reuse as hvt
    float* hvt = Ns;                         // 128 x 64
#pragma unroll
    for (int n = 0; n < 8; n++) {
        acc[n].x += bv.x; acc[n].y += bv.y; acc[n].z += bv.z; acc[n].w += bv.w;
        int node = base + ng * 8 + n;
        if (node < NN)
            ((float4*)g_hv)[(long)node * 16 + cg] = acc[n];
        *(float4*)&hvt[(ng * 8 + n) * NOUT + cg * 4] = acc[n];
    }
    __syncthreads();

    // per-node scalars: 8 warps x 16 nodes
    int wp = tid >> 5, l = tid & 31;
    float a1x = __ldg(&an[2*l]),      a1y = __ldg(&an[2*l+1]);
    float a2x = __ldg(&an[64 + 2*l]), a2y = __ldg(&an[64 + 2*l+1]);
#pragma unroll
    for (int i = 0; i < 16; i++) {
        int n = wp * 16 + i;
        int node = base + n;
        float2 h = ((const float2*)hvt)[n * 32 + l];
        float s1 = h.x * a1x + h.y * a1y;
        float s2 = h.x * a2x + h.y * a2y;
        float sq = h.x * h.x + h.y * h.y;
#pragma unroll
        for (int o = 16; o; o >>= 1) {
            s1 += __shfl_down_sync(FULLM, s1, o);
            s2 += __shfl_down_sync(FULLM, s2, o);
            sq += __shfl_down_sync(FULLM, sq, o);
        }
        if (l == 0 && node < NN) {
            g_s1[node] = s1; g_s2[node] = s2; g_hn[node] = sqrtf(sq);
        }
    }
}

// ---------------- k2: t[u] = edge_fts[u] . a[128:160], coalesced -----------------
__global__ void k2_edgedot(const float* __restrict__ ef,
                           const float* __restrict__ an) {
    int w = (blockIdx.x * blockDim.x + threadIdx.x) >> 5;
    int l = threadIdx.x & 31;
    int row0 = w * 4;
    if (row0 >= NE) return;
    float4 v = ((const float4*)ef)[(long)row0 * 8 + l];
    const float* a3 = an + 2 * NOUT;
    int q = l & 7;
    float s = v.x * __ldg(&a3[4*q])   + v.y * __ldg(&a3[4*q+1])
            + v.z * __ldg(&a3[4*q+2]) + v.w * __ldg(&a3[4*q+3]);
    s += __shfl_xor_sync(FULLM, s, 4);
    s += __shfl_xor_sync(FULLM, s, 2);
    s += __shfl_xor_sync(FULLM, s, 1);
    if (q == 0) g_t[row0 + (l >> 3)] = s;
}

// ---------------- k3: both directions per undirected edge ------------------------
__global__ void k3_att(const int* __restrict__ p) {
    int u = blockIdx.x * blockDim.x + threadIdx.x;
    if (u >= NE) return;
    int2 xy = __ldg(&((const int2*)p)[u]);
    float tu = g_t[u];
    float lg1 = __ldg(&g_s1[xy.x]) + __ldg(&g_s2[xy.y]) + tu;  // src=x,dst=y
    float lg2 = __ldg(&g_s1[xy.y]) + __ldg(&g_s2[xy.x]) + tu;  // src=y,dst=x
    float lr1 = (lg1 > 0.f) ? lg1 : ALPHA_L * lg1;
    float lr2 = (lg2 > 0.f) ? lg2 : ALPHA_L * lg2;
    g_lr[u]      = lr1;
    g_lr[u + NE] = lr2;
    atomicAdd(&g_attsum[xy.x], __expf(lr1));
    atomicAdd(&g_attsum[xy.y], __expf(lr2));
}

// ---------------- k4: msg scatter (vector RED) + variance partials ---------------
#define ED 4   // undirected edges per warp
__global__ void k4_scatter(const int* __restrict__ p) {
    __shared__ float ssum[8], ssq[8];
    int warp = (blockIdx.x * blockDim.x + threadIdx.x) >> 5;
    int l = threadIdx.x & 31;
    int half = l >> 4, q = l & 15;
    long base = (long)warp * ED;
    float vs = 0.f, vq = 0.f;
#pragma unroll
    for (int e = 0; e < ED; e++) {
        long u = base + e;
        if (u >= NE) break;
        int2 xy = __ldg(&((const int2*)p)[u]);
        float an1 = __ldg(&g_lr[u])      - __logf(__ldg(&g_attsum[xy.x]));
        float an2 = __ldg(&g_lr[u + NE]) - __logf(__ldg(&g_attsum[xy.y]));
        // lanes 0-15: msg[x] += h[y]*an1 ; lanes 16-31: msg[y] += h[x]*an2
        int gsrc = half ? xy.y : xy.x;
        int gdst = half ? xy.x : xy.y;
        float an = half ? an2 : an1;
        float4 h = __ldg(&((const float4*)g_hv)[(long)gdst * 16 + q]);
        red_v4(&g_msg[(long)gsrc * NOUT + q * 4],
               make_float4(h.x * an, h.y * an, h.z * an, h.w * an));
        if (l == 0) { vs += an1 + an2; vq += an1 * an1 + an2 * an2; }
    }
    if (l == 0) { ssum[threadIdx.x >> 5] = vs; ssq[threadIdx.x >> 5] = vq; }
    __syncthreads();
    if (threadIdx.x == 0) {
        float bs = 0.f, bq = 0.f;
#pragma unroll
        for (int i = 0; i < 8; i++) { bs += ssum[i]; bq += ssq[i]; }
        atomicAdd(&g_psum[blockIdx.x & (NPART - 1)], (double)bs);
        atomicAdd(&g_psq [blockIdx.x & (NPART - 1)], (double)bq);
    }
}

// ---------------- k5: variance -> out[NN*128] -------------------------------------
__global__ void k5_var(float* __restrict__ out) {
    __shared__ double s[NPART], q[NPART];
    int t = threadIdx.x;
    s[t] = g_psum[t]; q[t] = g_psq[t];
    __syncthreads();
    for (int o = NPART / 2; o; o >>= 1) {
        if (t < o) { s[t] += s[t + o]; q[t] += q[t + o]; }
        __syncthreads();
    }
    if (t == 0) {
        double E = (double)ND;
        double var = (q[0] - s[0] * s[0] / E) / (E - 1.0);
        out[(long)NN * 128] = (float)var;
    }
}

// ---------------- k6: final embed ---------------------------------------------------
__global__ void k6_final(float* __restrict__ out, const float* __restrict__ scale) {
    int w = (blockIdx.x * blockDim.x + threadIdx.x) >> 5;
    int l = threadIdx.x & 31;
    if (w >= NN) return;
    float2 m = ((const float2*)g_msg)[(long)w * 32 + l];
    float sq = m.x * m.x + m.y * m.y;
#pragma unroll
    for (int o = 16; o; o >>= 1) sq += __shfl_xor_sync(FULLM, sq, o);
    float r = g_hn[w] * __ldg(scale) / fmaxf(sqrtf(sq), EPSV);
    float2 h = ((const float2*)g_hv)[(long)w * 32 + l];
    float2* orow = (float2*)(out + (long)w * 128);
    orow[l]      = h;
    orow[32 + l] = make_float2(m.x * r, m.y * r);
}

// ---------------- launch --------------------------------------------------------------
extern "C" void kernel_launch(void* const* d_in, const int* in_sizes, int n_in,
                              void* d_out, int out_size) {
    const float* nf    = (const float*)d_in[0];
    const float* ef    = (const float*)d_in[1];
    const int*   edges = (const int*)  d_in[2];
    const float* W     = (const float*)d_in[3];
    const float* b     = (const float*)d_in[4];
    const float* an    = (const float*)d_in[5];
    const float* scale = (const float*)d_in[6];
    float* out = (float*)d_out;

    const int k1_smem = (8192 + 16384) * 4;  // 96 KB
    cudaFuncSetAttribute(k1_gemm, cudaFuncAttributeMaxDynamicSharedMemorySize, k1_smem);

    k0_zero   <<<512, 256>>>();
    k1_gemm   <<<(NN + 127)/128, 256, k1_smem>>>(nf, W, b, an);
    k2_edgedot<<<(NE/4 + 7)/8, 256>>>(ef, an);
    k3_att    <<<(NE + 255)/256, 256>>>(edges);
    k4_scatter<<<(NE + 8*ED - 1)/(8*ED), 256>>>(edges);   // 8 warps/block, 4 edges/warp
    k5_var    <<<1, NPART>>>(out);
    k6_final  <<<(NN*32 + 255)/256, 256>>>(out, scale);
}

// round 4
// speedup vs baseline: 1.8137x; 1.1143x over previous
#include <cuda_runtime.h>

#define NN      50000      // nodes
#define NIN     128        // node in-dim
#define NOUT    64         // node out-dim
#define EIN     32         // edge feat dim
#define NE      400000     // undirected edges
#define ND      (2*NE)     // directed edges
#define ALPHA_L 0.2f
#define EPSV    1e-12f
#define NPART   256
#define FULLM   0xffffffffu

// ---------------- scratch (device globals) -------------------------------------
__device__ __align__(16) float g_hv[NN * NOUT];   // h_v
__device__ __align__(16) float g_msg[NN * NOUT];  // segment sum by src
__device__ float  g_s1[NN];
__device__ float  g_s2[NN];
__device__ float  g_hn[NN];
__device__ float  g_attsum[NN];
__device__ float  g_lr[ND];
__device__ double g_psum[NPART];
__device__ double g_psq[NPART];

// vector RED: 4 floats in one L2 atomic op (sm_90+)
__device__ __forceinline__ void red_v4(float* addr, float4 v) {
    asm volatile("red.global.add.v4.f32 [%0], {%1,%2,%3,%4};"
                 :: "l"(addr), "f"(v.x), "f"(v.y), "f"(v.z), "f"(v.w) : "memory");
}

// ---------------- k1: zero prologue + GEMM + scalars + out[:,0:64] ---------------
// 256 threads, 128 nodes/block, thread tile 8 nodes x 4 cols.
__global__ void k1_gemm(const float* __restrict__ nf,
                        const float* __restrict__ W,
                        const float* __restrict__ b,
                        const float* __restrict__ an,
                        float* __restrict__ out) {
    extern __shared__ float sm[];
    float* Ws = sm;            // 8192 floats (32 KB)
    float* Ns = sm + 8192;     // 16384 floats (64 KB)
    int tid = threadIdx.x;
    int base = blockIdx.x * 128;
    int gid = blockIdx.x * 256 + tid;

    // prologue: zero attsum + variance partials (grid covers 100096 >= NN)
    if (gid < NN) g_attsum[gid] = 0.f;
    if (gid < NPART) { g_psum[gid] = 0.0; g_psq[gid] = 0.0; }

    for (int i = tid; i < (NIN * NOUT) / 4; i += 256)
        ((float4*)Ws)[i] = ((const float4*)W)[i];
    for (int i = tid; i < (128 * NIN) / 4; i += 256) {
        int node = base + (i >> 5);
        float4 v = make_float4(0.f, 0.f, 0.f, 0.f);
        if (node < NN) v = ((const float4*)nf)[(long)node * 32 + (i & 31)];
        ((float4*)Ns)[i] = v;
    }
    __syncthreads();

    int cg = tid & 15;         // 4 cols each
    int ng = tid >> 4;         // 8 nodes each
    const float* nb = &Ns[ng * 8 * NIN];

    float4 acc[8];
#pragma unroll
    for (int n = 0; n < 8; n++) acc[n] = make_float4(0.f, 0.f, 0.f, 0.f);

#pragma unroll 4
    for (int k = 0; k < NIN; k++) {
        float4 wv = *(const float4*)&Ws[k * NOUT + cg * 4];
#pragma unroll
        for (int n = 0; n < 8; n++) {
            float av = nb[n * NIN + k];
            acc[n].x += av * wv.x;
            acc[n].y += av * wv.y;
            acc[n].z += av * wv.z;
            acc[n].w += av * wv.w;
        }
    }

    float4 bv = *(const float4*)&b[cg * 4];
    __syncthreads();                         // done reading Ns; reuse as hvt
    float* hvt = Ns;
#pragma unroll
    for (int n = 0; n < 8; n++) {
        acc[n].x += bv.x; acc[n].y += bv.y; acc[n].z += bv.z; acc[n].w += bv.w;
        int node = base + ng * 8 + n;
        if (node < NN) {
            ((float4*)g_hv)[(long)node * 16 + cg] = acc[n];
            ((float4*)out) [(long)node * 32 + cg] = acc[n];   // out cols 0..63
        }
        *(float4*)&hvt[(ng * 8 + n) * NOUT + cg * 4] = acc[n];
    }
    __syncthreads();

    // per-node scalars: 8 warps x 16 nodes each
    int wp = tid >> 5, l = tid & 31;
    float a1x = __ldg(&an[2*l]),      a1y = __ldg(&an[2*l+1]);
    float a2x = __ldg(&an[64 + 2*l]), a2y = __ldg(&an[64 + 2*l+1]);
#pragma unroll
    for (int i = 0; i < 16; i++) {
        int n = wp * 16 + i;
        int node = base + n;
        float2 h = ((const float2*)hvt)[n * 32 + l];
        float s1 = h.x * a1x + h.y * a1y;
        float s2 = h.x * a2x + h.y * a2y;
        float sq = h.x * h.x + h.y * h.y;
#pragma unroll
        for (int o = 16; o; o >>= 1) {
            s1 += __shfl_down_sync(FULLM, s1, o);
            s2 += __shfl_down_sync(FULLM, s2, o);
            sq += __shfl_down_sync(FULLM, sq, o);
        }
        if (l == 0 && node < NN) {
            g_s1[node] = s1; g_s2[node] = s2; g_hn[node] = sqrtf(sq);
        }
    }
}

// ---------------- kE: edge dot + attention (both dirs) + zero g_msg --------------
// Warp handles 4 edges. Coalesced 512B edge-feature read, shuffle-reduce t,
// then lanes 0-7 handle 4 edges x 2 directions in parallel.
__global__ void kE_edge(const float* __restrict__ ef,
                        const float* __restrict__ an,
                        const int* __restrict__ p) {
    long gid = (long)blockIdx.x * blockDim.x + threadIdx.x;
    // zero msg: 3.2M threads cover 800000 float4s
    if (gid < (long)(NN * NOUT / 4))
        ((float4*)g_msg)[gid] = make_float4(0.f, 0.f, 0.f, 0.f);

    int w = (int)(gid >> 5);
    int l = threadIdx.x & 31;
    int row0 = w * 4;                      // NE % 4 == 0, grid exact
    float4 v = __ldg(&((const float4*)ef)[(long)row0 * 8 + l]);
    const float* a3 = an + 2 * NOUT;
    int q = l & 7;
    float s = v.x * __ldg(&a3[4*q])   + v.y * __ldg(&a3[4*q+1])
            + v.z * __ldg(&a3[4*q+2]) + v.w * __ldg(&a3[4*q+3]);
    s += __shfl_xor_sync(FULLM, s, 4);
    s += __shfl_xor_sync(FULLM, s, 2);
    s += __shfl_xor_sync(FULLM, s, 1);
    // lane l gets t of edge row0+(l&3) (held by lane (l&3)*8 group)
    float tu = __shfl_sync(FULLM, s, (l & 3) << 3);

    if (l < 8) {
        int u = row0 + (l & 3);
        int dir = l >> 2;                  // 0: src=x,dst=y ; 1: src=y,dst=x
        int2 xy = __ldg(&((const int2*)p)[u]);
        int src = dir ? xy.y : xy.x;
        int dst = dir ? xy.x : xy.y;
        float lg = __ldg(&g_s1[src]) + __ldg(&g_s2[dst]) + tu;
        float lr = (lg > 0.f) ? lg : ALPHA_L * lg;
        g_lr[u + dir * NE] = lr;
        atomicAdd(&g_attsum[src], __expf(lr));
    }
}

// ---------------- k4: msg scatter (vector RED, prefetched) + var partials --------
#define ED 4   // undirected edges per warp
__global__ void k4_scatter(const int* __restrict__ p) {
    __shared__ float ssum[8], ssq[8];
    int warp = (blockIdx.x * blockDim.x + threadIdx.x) >> 5;
    int l = threadIdx.x & 31;
    int half = l >> 4, q = l & 15;
    long base = (long)warp * ED;           // NE % ED == 0, grid exact

    int2  xy[ED];
    float l1[ED], l2[ED];
#pragma unroll
    for (int e = 0; e < ED; e++) {
        long u = base + e;
        xy[e] = __ldg(&((const int2*)p)[u]);
        l1[e] = __ldg(&g_lr[u]);
        l2[e] = __ldg(&g_lr[u + NE]);
    }
    float a1[ED], a2[ED];
    float4 h[ED];
#pragma unroll
    for (int e = 0; e < ED; e++) {
        a1[e] = __ldg(&g_attsum[xy[e].x]);
        a2[e] = __ldg(&g_attsum[xy[e].y]);
        int gdst = half ? xy[e].x : xy[e].y;
        h[e] = __ldg(&((const float4*)g_hv)[(long)gdst * 16 + q]);
    }
    float vs = 0.f, vq = 0.f;
#pragma unroll
    for (int e = 0; e < ED; e++) {
        float an1 = l1[e] - __logf(a1[e]);
        float an2 = l2[e] - __logf(a2[e]);
        float an  = half ? an2 : an1;
        int gsrc  = half ? xy[e].y : xy[e].x;
        red_v4(&g_msg[(long)gsrc * NOUT + q * 4],
               make_float4(h[e].x * an, h[e].y * an, h[e].z * an, h[e].w * an));
        if (l == 0) { vs += an1 + an2; vq += an1 * an1 + an2 * an2; }
    }
    if (l == 0) { ssum[threadIdx.x >> 5] = vs; ssq[threadIdx.x >> 5] = vq; }
    __syncthreads();
    if (threadIdx.x == 0) {
        float bs = 0.f, bq = 0.f;
#pragma unroll
        for (int i = 0; i < 8; i++) { bs += ssum[i]; bq += ssq[i]; }
        atomicAdd(&g_psum[blockIdx.x & (NPART - 1)], (double)bs);
        atomicAdd(&g_psq [blockIdx.x & (NPART - 1)], (double)bq);
    }
}

// ---------------- k6: agg normalize + out[:,64:128]; block 0 also does variance --
__global__ void k6_final(float* __restrict__ out, const float* __restrict__ scale) {
    __shared__ double sd[NPART], qd[NPART];
    int w = (blockIdx.x * blockDim.x + threadIdx.x) >> 5;
    int l = threadIdx.x & 31;
    if (w < NN) {
        float2 m = ((const float2*)g_msg)[(long)w * 32 + l];
        float sq = m.x * m.x + m.y * m.y;
#pragma unroll
        for (int o = 16; o; o >>= 1) sq += __shfl_xor_sync(FULLM, sq, o);
        float r = g_hn[w] * __ldg(scale) / fmaxf(sqrtf(sq), EPSV);
        ((float2*)(out + (long)w * 128))[32 + l] = make_float2(m.x * r, m.y * r);
    }
    if (blockIdx.x == 0) {
        int t = threadIdx.x;
        sd[t] = g_psum[t]; qd[t] = g_psq[t];
        __syncthreads();
        for (int o = NPART / 2; o; o >>= 1) {
            if (t < o) { sd[t] += sd[t + o]; qd[t] += qd[t + o]; }
            __syncthreads();
        }
        if (t == 0) {
            double E = (double)ND;
            double var = (qd[0] - sd[0] * sd[0] / E) / (E - 1.0);
            out[(long)NN * 128] = (float)var;
        }
    }
}

// ---------------- launch --------------------------------------------------------------
extern "C" void kernel_launch(void* const* d_in, const int* in_sizes, int n_in,
                              void* d_out, int out_size) {
    const float* nf    = (const float*)d_in[0];
    const float* ef    = (const float*)d_in[1];
    const int*   edges = (const int*)  d_in[2];
    const float* W     = (const float*)d_in[3];
    const float* b     = (const float*)d_in[4];
    const float* an    = (const float*)d_in[5];
    const float* scale = (const float*)d_in[6];
    float* out = (float*)d_out;

    const int k1_smem = (8192 + 16384) * 4;  // 96 KB
    cudaFuncSetAttribute(k1_gemm, cudaFuncAttributeMaxDynamicSharedMemorySize, k1_smem);

    k1_gemm   <<<(NN + 127)/128, 256, k1_smem>>>(nf, W, b, an, out);
    kE_edge   <<<NE/4/8, 256>>>(ef, an, edges);          // 12500 blocks, warp = 4 edges
    k4_scatter<<<NE/(8*ED), 256>>>(edges);               // 12500 blocks
    k6_final  <<<NN*32/256, 256>>>(out, scale);          // 6250 blocks
}